// round 5
// baseline (speedup 1.0000x reference)
#include <cuda_runtime.h>
#include <math.h>

#define B_  2
#define S_  2048
#define D_  2048
#define H_  16
#define HD_ 128

// ---------------- scratch (device globals: no allocation allowed) -------------
__device__ float g_Q[(size_t)B_ * H_ * S_ * HD_];   // [B,H,S,hd]
__device__ float g_K[(size_t)B_ * H_ * S_ * HD_];
__device__ float g_V[(size_t)B_ * H_ * S_ * HD_];
__device__ float g_att[(size_t)B_ * S_ * D_];       // [B,S,D] attention output
__device__ float g_cos[S_ * 64];
__device__ float g_sin[S_ * 64];

// ---------------- RoPE tables -------------------------------------------------
// Mimic reference fp32 rounding: angle = fp32(s * fp32(inv_freq)); trig in double.
__global__ void rope_tables_kernel() {
    int idx = blockIdx.x * blockDim.x + threadIdx.x;
    if (idx >= S_ * 64) return;
    int s = idx >> 6, j = idx & 63;
    float invf = (float)(1.0 / pow(10000.0, (double)(2 * j) / 128.0));
    float ang_f = (float)s * invf;
    double ang = (double)ang_f;
    g_cos[idx] = (float)cos(ang);
    g_sin[idx] = (float)sin(ang);
}

// Apply RoPE in place to g_Q and g_K. One thread per (row, j) pair, j in [0,64).
__global__ void rope_apply_kernel() {
    int idx = blockIdx.x * blockDim.x + threadIdx.x;
    const int total = B_ * H_ * S_ * 64;
    float* T = (idx < total) ? g_Q : g_K;
    int p = (idx < total) ? idx : idx - total;
    int j = p & 63;
    int row = p >> 6;                // (b*H + h)*S + s
    int s = row & (S_ - 1);
    size_t base = (size_t)row * HD_ + j;
    float c  = g_cos[(s << 6) + j];
    float sn = g_sin[(s << 6) + j];
    float x0 = T[base];
    float x1 = T[base + 64];
    T[base]      = x0 * c - x1 * sn;
    T[base + 64] = x1 * c + x0 * sn;
}

// ---------------- SGEMM: C[m,n] = sum_k A[m,k] * W[n,k] ----------------------
// M=4096, N=2048, K=2048. 128x128 tile, BK=32, 256 threads, 8x8 micro-tile.
// mode 0: C row-major [M,N].  mode 1: head layout [B,H,S,hd].
#define GBK 32
#define GPAD 132

__global__ void __launch_bounds__(256) sgemm_kernel(
    const float* __restrict__ A, const float* __restrict__ W,
    float* __restrict__ C, int mode)
{
    __shared__ float As[GBK * GPAD];
    __shared__ float Ws[GBK * GPAD];
    const int K = D_;
    int tid = threadIdx.x;
    int tx = tid & 15, ty = tid >> 4;
    int m0 = blockIdx.y * 128, n0 = blockIdx.x * 128;

    float acc[8][8];
#pragma unroll
    for (int i = 0; i < 8; i++)
#pragma unroll
        for (int j = 0; j < 8; j++) acc[i][j] = 0.f;

    const float* Ablk = A + (size_t)m0 * K;
    const float* Wblk = W + (size_t)n0 * K;

    for (int k0 = 0; k0 < K; k0 += GBK) {
#pragma unroll
        for (int r = 0; r < 4; r++) {
            int idx = tid + 256 * r;          // float4 index, 1024 total
            int row = idx >> 3;               // 8 f4 per row (32 floats)
            int col = (idx & 7) << 2;
            float4 a = *(const float4*)(Ablk + (size_t)row * K + k0 + col);
            As[(col + 0) * GPAD + row] = a.x;
            As[(col + 1) * GPAD + row] = a.y;
            As[(col + 2) * GPAD + row] = a.z;
            As[(col + 3) * GPAD + row] = a.w;
            float4 w = *(const float4*)(Wblk + (size_t)row * K + k0 + col);
            Ws[(col + 0) * GPAD + row] = w.x;
            Ws[(col + 1) * GPAD + row] = w.y;
            Ws[(col + 2) * GPAD + row] = w.z;
            Ws[(col + 3) * GPAD + row] = w.w;
        }
        __syncthreads();
#pragma unroll 8
        for (int kk = 0; kk < GBK; kk++) {
            float ra[8], rb[8];
            *(float4*)&ra[0] = *(const float4*)&As[kk * GPAD + ty * 8];
            *(float4*)&ra[4] = *(const float4*)&As[kk * GPAD + ty * 8 + 4];
            *(float4*)&rb[0] = *(const float4*)&Ws[kk * GPAD + tx * 8];
            *(float4*)&rb[4] = *(const float4*)&Ws[kk * GPAD + tx * 8 + 4];
#pragma unroll
            for (int i = 0; i < 8; i++)
#pragma unroll
                for (int j = 0; j < 8; j++)
                    acc[i][j] += ra[i] * rb[j];
        }
        __syncthreads();
    }

#pragma unroll
    for (int i = 0; i < 8; i++) {
        int m = m0 + ty * 8 + i;
#pragma unroll
        for (int j = 0; j < 8; j++) {
            int n = n0 + tx * 8 + j;
            if (mode == 0) {
                C[(size_t)m * D_ + n] = acc[i][j];
            } else {
                int b = m >> 11, s = m & (S_ - 1);
                int h = n >> 7,  d = n & 127;
                C[(((size_t)b * H_ + h) * S_ + s) * HD_ + d] = acc[i][j];
            }
        }
    }
}

// ---------------- Flash attention (fp32) -------------------------------------
// Block: one head, 128 query rows. 256 threads (16x16).
// Per thread: S fragment 8 rows x 4 cols (cols tx+16j), O fragment 8x8 (cols tx+16u).
#define BQ  128
#define BKT 64
// smem: Qs[128][129] | KPs = union(Ks[64][129], Ps[128][65]) | Vs[64][129]
#define QS_FLOATS  (BQ * 129)
#define KPS_FLOATS (BQ * 65)          /* 8320 >= 64*129=8256 */
#define VS_FLOATS  (BKT * 129)
#define ATT_SMEM_BYTES ((QS_FLOATS + KPS_FLOATS + VS_FLOATS) * 4)

__global__ void __launch_bounds__(256) attn_kernel(const int* __restrict__ mask)
{
    extern __shared__ float sm[];
    float* Qs  = sm;
    float* KPs = sm + QS_FLOATS;
    float* Vs  = KPs + KPS_FLOATS;

    int bh = blockIdx.y;               // b*H + h
    int b = bh >> 4, h = bh & 15;
    int q0 = blockIdx.x * BQ;
    int tid = threadIdx.x;
    int tx = tid & 15, ty = tid >> 4;
    const float scale = 0.08838834764831843f;   // 1/sqrt(128)

    const float* Qg = g_Q + (size_t)bh * S_ * HD_ + (size_t)q0 * HD_;
    const float* Kg = g_K + (size_t)bh * S_ * HD_;
    const float* Vg = g_V + (size_t)bh * S_ * HD_;
    const int*   Mg = mask + (size_t)b * S_ * S_ + (size_t)q0 * S_;

    // Load Q tile, pre-scaled. 128x128 floats = 4096 float4, 16 per thread.
#pragma unroll
    for (int r = 0; r < 16; r++) {
        int idx = tid + 256 * r;
        int row = idx >> 5;            // 32 f4 per row
        int col = (idx & 31) << 2;
        float4 v = *(const float4*)(Qg + (size_t)row * HD_ + col);
        float* dst = Qs + row * 129 + col;
        dst[0] = v.x * scale; dst[1] = v.y * scale;
        dst[2] = v.z * scale; dst[3] = v.w * scale;
    }

    float m_run[8], l_run[8], accO[8][8];
#pragma unroll
    for (int i = 0; i < 8; i++) {
        m_run[i] = -INFINITY;
        l_run[i] = 0.f;
#pragma unroll
        for (int u = 0; u < 8; u++) accO[i][u] = 0.f;
    }

    for (int kt = 0; kt < S_; kt += BKT) {
        __syncthreads();               // previous PV reads of KPs/Vs done
        // Load K and V tiles: 64x128 floats = 2048 float4 each, 8 per thread.
#pragma unroll
        for (int r = 0; r < 8; r++) {
            int idx = tid + 256 * r;
            int row = idx >> 5;
            int col = (idx & 31) << 2;
            float4 kv = *(const float4*)(Kg + (size_t)(kt + row) * HD_ + col);
            float* kd = KPs + row * 129 + col;
            kd[0] = kv.x; kd[1] = kv.y; kd[2] = kv.z; kd[3] = kv.w;
            float4 vv = *(const float4*)(Vg + (size_t)(kt + row) * HD_ + col);
            float* vd = Vs + row * 129 + col;
            vd[0] = vv.x; vd[1] = vv.y; vd[2] = vv.z; vd[3] = vv.w;
        }
        __syncthreads();

        // S = (Q*scale) K^T : sv[8][4]
        float sv[8][4];
#pragma unroll
        for (int i = 0; i < 8; i++)
#pragma unroll
            for (int j = 0; j < 4; j++) sv[i][j] = 0.f;
#pragma unroll 4
        for (int d = 0; d < HD_; d++) {
            float qv[8], kv[4];
#pragma unroll
            for (int i = 0; i < 8; i++) qv[i] = Qs[(ty * 8 + i) * 129 + d];
#pragma unroll
            for (int j = 0; j < 4; j++) kv[j] = KPs[(tx + 16 * j) * 129 + d];
#pragma unroll
            for (int i = 0; i < 8; i++)
#pragma unroll
                for (int j = 0; j < 4; j++)
                    sv[i][j] += qv[i] * kv[j];
        }
        // mask (reference: score = -inf where mask==0)
#pragma unroll
        for (int i = 0; i < 8; i++)
#pragma unroll
            for (int j = 0; j < 4; j++)
                if (Mg[(size_t)(ty * 8 + i) * S_ + kt + tx + 16 * j] == 0)
                    sv[i][j] = -1e30f;

        // online softmax; row stats replicated across the 16-lane tx group
#pragma unroll
        for (int i = 0; i < 8; i++) {
            float mx = sv[i][0];
#pragma unroll
            for (int j = 1; j < 4; j++) mx = fmaxf(mx, sv[i][j]);
#pragma unroll
            for (int o = 8; o; o >>= 1)
                mx = fmaxf(mx, __shfl_xor_sync(0xffffffffu, mx, o));
            float mnew = fmaxf(m_run[i], mx);
            float corr = __expf(m_run[i] - mnew);
            m_run[i] = mnew;
            float ls = 0.f;
#pragma unroll
            for (int j = 0; j < 4; j++) {
                float p = __expf(sv[i][j] - mnew);
                sv[i][j] = p;
                ls += p;
            }
#pragma unroll
            for (int o = 8; o; o >>= 1)
                ls += __shfl_xor_sync(0xffffffffu, ls, o);
            l_run[i] = l_run[i] * corr + ls;
#pragma unroll
            for (int u = 0; u < 8; u++) accO[i][u] *= corr;
        }

        __syncthreads();               // all reads of KPs (as K) done
        // stage P into KPs as [128][65]
#pragma unroll
        for (int i = 0; i < 8; i++)
#pragma unroll
            for (int j = 0; j < 4; j++)
                KPs[(ty * 8 + i) * 65 + tx + 16 * j] = sv[i][j];
        __syncthreads();

        // O += P V
#pragma unroll 4
        for (int kk = 0; kk < BKT; kk++) {
            float pv[8], vv[8];
#pragma unroll
            for (int i = 0; i < 8; i++) pv[i] = KPs[(ty * 8 + i) * 65 + kk];
#pragma unroll
            for (int u = 0; u < 8; u++) vv[u] = Vs[kk * 129 + tx + 16 * u];
#pragma unroll
            for (int i = 0; i < 8; i++)
#pragma unroll
                for (int u = 0; u < 8; u++)
                    accO[i][u] += pv[i] * vv[u];
        }
    }

    // normalize + write to [B,S,D] layout
    float* Og = g_att + ((size_t)b * S_ + q0) * D_ + h * HD_;
#pragma unroll
    for (int i = 0; i < 8; i++) {
        float inv = 1.0f / l_run[i];
        int row = ty * 8 + i;
#pragma unroll
        for (int u = 0; u < 8; u++)
            Og[(size_t)row * D_ + tx + 16 * u] = accO[i][u] * inv;
    }
}

// ---------------- launch ------------------------------------------------------
extern "C" void kernel_launch(void* const* d_in, const int* in_sizes, int n_in,
                              void* d_out, int out_size)
{
    const float* query = (const float*)d_in[0];
    const float* key   = (const float*)d_in[1];
    const float* value = (const float*)d_in[2];
    const int*   mask  = (const int*)d_in[3];
    const float* wq    = (const float*)d_in[4];
    const float* wk    = (const float*)d_in[5];
    const float* wv    = (const float*)d_in[6];
    const float* wo    = (const float*)d_in[7];
    float* out = (float*)d_out;

    float *gQ, *gK, *gV, *gA;
    cudaGetSymbolAddress((void**)&gQ, g_Q);
    cudaGetSymbolAddress((void**)&gK, g_K);
    cudaGetSymbolAddress((void**)&gV, g_V);
    cudaGetSymbolAddress((void**)&gA, g_att);

    cudaFuncSetAttribute(attn_kernel,
                         cudaFuncAttributeMaxDynamicSharedMemorySize,
                         ATT_SMEM_BYTES);

    // RoPE tables
    rope_tables_kernel<<<(S_ * 64 + 255) / 256, 256>>>();

    // Projections (write head layout [B,H,S,hd])
    dim3 pg(D_ / 128, (B_ * S_) / 128);     // (16, 32)
    sgemm_kernel<<<pg, 256>>>(query, wq, gQ, 1);
    sgemm_kernel<<<pg, 256>>>(key,   wk, gK, 1);
    sgemm_kernel<<<pg, 256>>>(value, wv, gV, 1);

    // RoPE on Q and K (in place)
    rope_apply_kernel<<<(2 * B_ * H_ * S_ * 64) / 256, 256>>>();

    // Attention
    attn_kernel<<<dim3(S_ / BQ, B_ * H_), 256, ATT_SMEM_BYTES>>>(mask);

    // Output projection (plain [B,S,D] into d_out)
    sgemm_kernel<<<pg, 256>>>(gA, wo, out, 0);
}

// round 6
// speedup vs baseline: 1.0017x; 1.0017x over previous
#include <cuda_runtime.h>
#include <math.h>

#define B_  2
#define S_  2048
#define D_  2048
#define H_  16
#define HD_ 128

// ---------------- scratch (device globals: no allocation allowed) -------------
__device__ float g_Q[(size_t)B_ * H_ * S_ * HD_];   // [B,H,S,hd]
__device__ float g_K[(size_t)B_ * H_ * S_ * HD_];
__device__ float g_V[(size_t)B_ * H_ * S_ * HD_];
__device__ float g_att[(size_t)B_ * S_ * D_];       // [B,S,D] attention output
__device__ float g_cos[S_ * 64];
__device__ float g_sin[S_ * 64];

// ---------------- RoPE tables -------------------------------------------------
// Mimic reference fp32 rounding: angle = fp32(s * fp32(inv_freq)); trig in double.
__global__ void rope_tables_kernel() {
    int idx = blockIdx.x * blockDim.x + threadIdx.x;
    if (idx >= S_ * 64) return;
    int s = idx >> 6, j = idx & 63;
    float invf = (float)(1.0 / pow(10000.0, (double)(2 * j) / 128.0));
    float ang_f = (float)s * invf;
    double ang = (double)ang_f;
    g_cos[idx] = (float)cos(ang);
    g_sin[idx] = (float)sin(ang);
}

// Apply RoPE in place to g_Q and g_K. One thread per (row, j) pair, j in [0,64).
__global__ void rope_apply_kernel() {
    int idx = blockIdx.x * blockDim.x + threadIdx.x;
    const int total = B_ * H_ * S_ * 64;
    float* T = (idx < total) ? g_Q : g_K;
    int p = (idx < total) ? idx : idx - total;
    int j = p & 63;
    int row = p >> 6;                // (b*H + h)*S + s
    int s = row & (S_ - 1);
    size_t base = (size_t)row * HD_ + j;
    float c  = g_cos[(s << 6) + j];
    float sn = g_sin[(s << 6) + j];
    float x0 = T[base];
    float x1 = T[base + 64];
    T[base]      = x0 * c - x1 * sn;
    T[base + 64] = x1 * c + x0 * sn;
}

// ---------------- SGEMM: C[m,n] = sum_k A[m,k] * W[n,k] ----------------------
// M=4096, N=2048, K=2048. 128x128 tile, BK=32, 256 threads, 8x8 micro-tile.
// mode 0: C row-major [M,N].  mode 1: head layout [B,H,S,hd].
#define GBK 32
#define GPAD 132

__global__ void __launch_bounds__(256) sgemm_kernel(
    const float* __restrict__ A, const float* __restrict__ W,
    float* __restrict__ C, int mode)
{
    __shared__ float As[GBK * GPAD];
    __shared__ float Ws[GBK * GPAD];
    const int K = D_;
    int tid = threadIdx.x;
    int tx = tid & 15, ty = tid >> 4;
    int m0 = blockIdx.y * 128, n0 = blockIdx.x * 128;

    float acc[8][8];
#pragma unroll
    for (int i = 0; i < 8; i++)
#pragma unroll
        for (int j = 0; j < 8; j++) acc[i][j] = 0.f;

    const float* Ablk = A + (size_t)m0 * K;
    const float* Wblk = W + (size_t)n0 * K;

    for (int k0 = 0; k0 < K; k0 += GBK) {
#pragma unroll
        for (int r = 0; r < 4; r++) {
            int idx = tid + 256 * r;          // float4 index, 1024 total
            int row = idx >> 3;               // 8 f4 per row (32 floats)
            int col = (idx & 7) << 2;
            float4 a = *(const float4*)(Ablk + (size_t)row * K + k0 + col);
            As[(col + 0) * GPAD + row] = a.x;
            As[(col + 1) * GPAD + row] = a.y;
            As[(col + 2) * GPAD + row] = a.z;
            As[(col + 3) * GPAD + row] = a.w;
            float4 w = *(const float4*)(Wblk + (size_t)row * K + k0 + col);
            Ws[(col + 0) * GPAD + row] = w.x;
            Ws[(col + 1) * GPAD + row] = w.y;
            Ws[(col + 2) * GPAD + row] = w.z;
            Ws[(col + 3) * GPAD + row] = w.w;
        }
        __syncthreads();
#pragma unroll 8
        for (int kk = 0; kk < GBK; kk++) {
            float ra[8], rb[8];
            *(float4*)&ra[0] = *(const float4*)&As[kk * GPAD + ty * 8];
            *(float4*)&ra[4] = *(const float4*)&As[kk * GPAD + ty * 8 + 4];
            *(float4*)&rb[0] = *(const float4*)&Ws[kk * GPAD + tx * 8];
            *(float4*)&rb[4] = *(const float4*)&Ws[kk * GPAD + tx * 8 + 4];
#pragma unroll
            for (int i = 0; i < 8; i++)
#pragma unroll
                for (int j = 0; j < 8; j++)
                    acc[i][j] += ra[i] * rb[j];
        }
        __syncthreads();
    }

#pragma unroll
    for (int i = 0; i < 8; i++) {
        int m = m0 + ty * 8 + i;
#pragma unroll
        for (int j = 0; j < 8; j++) {
            int n = n0 + tx * 8 + j;
            if (mode == 0) {
                C[(size_t)m * D_ + n] = acc[i][j];
            } else {
                int b = m >> 11, s = m & (S_ - 1);
                int h = n >> 7,  d = n & 127;
                C[(((size_t)b * H_ + h) * S_ + s) * HD_ + d] = acc[i][j];
            }
        }
    }
}

// ---------------- Flash attention (fp32) -------------------------------------
// Block: one head, 128 query rows. 256 threads (16x16).
// Per thread: S fragment 8 rows x 4 cols (cols tx+16j), O fragment 8x8 (cols tx+16u).
#define BQ  128
#define BKT 64
// smem: Qs[128][129] | KPs = union(Ks[64][129], Ps[128][65]) | Vs[64][129]
#define QS_FLOATS  (BQ * 129)
#define KPS_FLOATS (BQ * 65)          /* 8320 >= 64*129=8256 */
#define VS_FLOATS  (BKT * 129)
#define ATT_SMEM_BYTES ((QS_FLOATS + KPS_FLOATS + VS_FLOATS) * 4)

__global__ void __launch_bounds__(256) attn_kernel(const int* __restrict__ mask)
{
    extern __shared__ float sm[];
    float* Qs  = sm;
    float* KPs = sm + QS_FLOATS;
    float* Vs  = KPs + KPS_FLOATS;

    int bh = blockIdx.y;               // b*H + h
    int b = bh >> 4, h = bh & 15;
    int q0 = blockIdx.x * BQ;
    int tid = threadIdx.x;
    int tx = tid & 15, ty = tid >> 4;
    const float scale = 0.08838834764831843f;   // 1/sqrt(128)

    const float* Qg = g_Q + (size_t)bh * S_ * HD_ + (size_t)q0 * HD_;
    const float* Kg = g_K + (size_t)bh * S_ * HD_;
    const float* Vg = g_V + (size_t)bh * S_ * HD_;
    const int*   Mg = mask + (size_t)b * S_ * S_ + (size_t)q0 * S_;

    // Load Q tile, pre-scaled. 128x128 floats = 4096 float4, 16 per thread.
#pragma unroll
    for (int r = 0; r < 16; r++) {
        int idx = tid + 256 * r;
        int row = idx >> 5;            // 32 f4 per row
        int col = (idx & 31) << 2;
        float4 v = *(const float4*)(Qg + (size_t)row * HD_ + col);
        float* dst = Qs + row * 129 + col;
        dst[0] = v.x * scale; dst[1] = v.y * scale;
        dst[2] = v.z * scale; dst[3] = v.w * scale;
    }

    float m_run[8], l_run[8], accO[8][8];
#pragma unroll
    for (int i = 0; i < 8; i++) {
        m_run[i] = -INFINITY;
        l_run[i] = 0.f;
#pragma unroll
        for (int u = 0; u < 8; u++) accO[i][u] = 0.f;
    }

    for (int kt = 0; kt < S_; kt += BKT) {
        __syncthreads();               // previous PV reads of KPs/Vs done
        // Load K and V tiles: 64x128 floats = 2048 float4 each, 8 per thread.
#pragma unroll
        for (int r = 0; r < 8; r++) {
            int idx = tid + 256 * r;
            int row = idx >> 5;
            int col = (idx & 31) << 2;
            float4 kv = *(const float4*)(Kg + (size_t)(kt + row) * HD_ + col);
            float* kd = KPs + row * 129 + col;
            kd[0] = kv.x; kd[1] = kv.y; kd[2] = kv.z; kd[3] = kv.w;
            float4 vv = *(const float4*)(Vg + (size_t)(kt + row) * HD_ + col);
            float* vd = Vs + row * 129 + col;
            vd[0] = vv.x; vd[1] = vv.y; vd[2] = vv.z; vd[3] = vv.w;
        }
        __syncthreads();

        // S = (Q*scale) K^T : sv[8][4]
        float sv[8][4];
#pragma unroll
        for (int i = 0; i < 8; i++)
#pragma unroll
            for (int j = 0; j < 4; j++) sv[i][j] = 0.f;
#pragma unroll 4
        for (int d = 0; d < HD_; d++) {
            float qv[8], kv[4];
#pragma unroll
            for (int i = 0; i < 8; i++) qv[i] = Qs[(ty * 8 + i) * 129 + d];
#pragma unroll
            for (int j = 0; j < 4; j++) kv[j] = KPs[(tx + 16 * j) * 129 + d];
#pragma unroll
            for (int i = 0; i < 8; i++)
#pragma unroll
                for (int j = 0; j < 4; j++)
                    sv[i][j] += qv[i] * kv[j];
        }
        // mask (reference: score = -inf where mask==0)
#pragma unroll
        for (int i = 0; i < 8; i++)
#pragma unroll
            for (int j = 0; j < 4; j++)
                if (Mg[(size_t)(ty * 8 + i) * S_ + kt + tx + 16 * j] == 0)
                    sv[i][j] = -1e30f;

        // online softmax; row stats replicated across the 16-lane tx group
#pragma unroll
        for (int i = 0; i < 8; i++) {
            float mx = sv[i][0];
#pragma unroll
            for (int j = 1; j < 4; j++) mx = fmaxf(mx, sv[i][j]);
#pragma unroll
            for (int o = 8; o; o >>= 1)
                mx = fmaxf(mx, __shfl_xor_sync(0xffffffffu, mx, o));
            float mnew = fmaxf(m_run[i], mx);
            float corr = __expf(m_run[i] - mnew);
            m_run[i] = mnew;
            float ls = 0.f;
#pragma unroll
            for (int j = 0; j < 4; j++) {
                float p = __expf(sv[i][j] - mnew);
                sv[i][j] = p;
                ls += p;
            }
#pragma unroll
            for (int o = 8; o; o >>= 1)
                ls += __shfl_xor_sync(0xffffffffu, ls, o);
            l_run[i] = l_run[i] * corr + ls;
#pragma unroll
            for (int u = 0; u < 8; u++) accO[i][u] *= corr;
        }

        __syncthreads();               // all reads of KPs (as K) done
        // stage P into KPs as [128][65]
#pragma unroll
        for (int i = 0; i < 8; i++)
#pragma unroll
            for (int j = 0; j < 4; j++)
                KPs[(ty * 8 + i) * 65 + tx + 16 * j] = sv[i][j];
        __syncthreads();

        // O += P V
#pragma unroll 4
        for (int kk = 0; kk < BKT; kk++) {
            float pv[8], vv[8];
#pragma unroll
            for (int i = 0; i < 8; i++) pv[i] = KPs[(ty * 8 + i) * 65 + kk];
#pragma unroll
            for (int u = 0; u < 8; u++) vv[u] = Vs[kk * 129 + tx + 16 * u];
#pragma unroll
            for (int i = 0; i < 8; i++)
#pragma unroll
                for (int u = 0; u < 8; u++)
                    accO[i][u] += pv[i] * vv[u];
        }
    }

    // normalize + write to [B,S,D] layout
    float* Og = g_att + ((size_t)b * S_ + q0) * D_ + h * HD_;
#pragma unroll
    for (int i = 0; i < 8; i++) {
        float inv = 1.0f / l_run[i];
        int row = ty * 8 + i;
#pragma unroll
        for (int u = 0; u < 8; u++)
            Og[(size_t)row * D_ + tx + 16 * u] = accO[i][u] * inv;
    }
}

// ---------------- launch ------------------------------------------------------
extern "C" void kernel_launch(void* const* d_in, const int* in_sizes, int n_in,
                              void* d_out, int out_size)
{
    const float* query = (const float*)d_in[0];
    const float* key   = (const float*)d_in[1];
    const float* value = (const float*)d_in[2];
    const int*   mask  = (const int*)d_in[3];
    const float* wq    = (const float*)d_in[4];
    const float* wk    = (const float*)d_in[5];
    const float* wv    = (const float*)d_in[6];
    const float* wo    = (const float*)d_in[7];
    float* out = (float*)d_out;

    float *gQ, *gK, *gV, *gA;
    cudaGetSymbolAddress((void**)&gQ, g_Q);
    cudaGetSymbolAddress((void**)&gK, g_K);
    cudaGetSymbolAddress((void**)&gV, g_V);
    cudaGetSymbolAddress((void**)&gA, g_att);

    cudaFuncSetAttribute(attn_kernel,
                         cudaFuncAttributeMaxDynamicSharedMemorySize,
                         ATT_SMEM_BYTES);

    // RoPE tables
    rope_tables_kernel<<<(S_ * 64 + 255) / 256, 256>>>();

    // Projections (write head layout [B,H,S,hd])
    dim3 pg(D_ / 128, (B_ * S_) / 128);     // (16, 32)
    sgemm_kernel<<<pg, 256>>>(query, wq, gQ, 1);
    sgemm_kernel<<<pg, 256>>>(key,   wk, gK, 1);
    sgemm_kernel<<<pg, 256>>>(value, wv, gV, 1);

    // RoPE on Q and K (in place)
    rope_apply_kernel<<<(2 * B_ * H_ * S_ * 64) / 256, 256>>>();

    // Attention
    attn_kernel<<<dim3(S_ / BQ, B_ * H_), 256, ATT_SMEM_BYTES>>>(mask);

    // Output projection (plain [B,S,D] into d_out)
    sgemm_kernel<<<pg, 256>>>(gA, wo, out, 0);
}

// round 7
// speedup vs baseline: 1.0018x; 1.0001x over previous
#include <cuda_runtime.h>
#include <math.h>

#define B_  2
#define S_  2048
#define D_  2048
#define H_  16
#define HD_ 128

// ---------------- scratch (device globals: no allocation allowed) -------------
__device__ float g_Q[(size_t)B_ * H_ * S_ * HD_];   // [B,H,S,hd]
__device__ float g_K[(size_t)B_ * H_ * S_ * HD_];
__device__ float g_V[(size_t)B_ * H_ * S_ * HD_];
__device__ float g_att[(size_t)B_ * S_ * D_];       // [B,S,D] attention output
__device__ float g_cos[S_ * 64];
__device__ float g_sin[S_ * 64];

// ---------------- RoPE tables -------------------------------------------------
// Mimic reference fp32 rounding: angle = fp32(s * fp32(inv_freq)); trig in double.
__global__ void rope_tables_kernel() {
    int idx = blockIdx.x * blockDim.x + threadIdx.x;
    if (idx >= S_ * 64) return;
    int s = idx >> 6, j = idx & 63;
    float invf = (float)(1.0 / pow(10000.0, (double)(2 * j) / 128.0));
    float ang_f = (float)s * invf;
    double ang = (double)ang_f;
    g_cos[idx] = (float)cos(ang);
    g_sin[idx] = (float)sin(ang);
}

// Apply RoPE in place to g_Q and g_K. One thread per (row, j) pair, j in [0,64).
__global__ void rope_apply_kernel() {
    int idx = blockIdx.x * blockDim.x + threadIdx.x;
    const int total = B_ * H_ * S_ * 64;
    float* T = (idx < total) ? g_Q : g_K;
    int p = (idx < total) ? idx : idx - total;
    int j = p & 63;
    int row = p >> 6;                // (b*H + h)*S + s
    int s = row & (S_ - 1);
    size_t base = (size_t)row * HD_ + j;
    float c  = g_cos[(s << 6) + j];
    float sn = g_sin[(s << 6) + j];
    float x0 = T[base];
    float x1 = T[base + 64];
    T[base]      = x0 * c - x1 * sn;
    T[base + 64] = x1 * c + x0 * sn;
}

// ---------------- SGEMM: C[m,n] = sum_k A[m,k] * W[n,k] ----------------------
// M=4096, N=2048, K=2048. 128x128 tile, BK=32, 256 threads, 8x8 micro-tile.
// mode 0: C row-major [M,N].  mode 1: head layout [B,H,S,hd].
#define GBK 32
#define GPAD 132

__global__ void __launch_bounds__(256) sgemm_kernel(
    const float* __restrict__ A, const float* __restrict__ W,
    float* __restrict__ C, int mode)
{
    __shared__ float As[GBK * GPAD];
    __shared__ float Ws[GBK * GPAD];
    const int K = D_;
    int tid = threadIdx.x;
    int tx = tid & 15, ty = tid >> 4;
    int m0 = blockIdx.y * 128, n0 = blockIdx.x * 128;

    float acc[8][8];
#pragma unroll
    for (int i = 0; i < 8; i++)
#pragma unroll
        for (int j = 0; j < 8; j++) acc[i][j] = 0.f;

    const float* Ablk = A + (size_t)m0 * K;
    const float* Wblk = W + (size_t)n0 * K;

    for (int k0 = 0; k0 < K; k0 += GBK) {
#pragma unroll
        for (int r = 0; r < 4; r++) {
            int idx = tid + 256 * r;          // float4 index, 1024 total
            int row = idx >> 3;               // 8 f4 per row (32 floats)
            int col = (idx & 7) << 2;
            float4 a = *(const float4*)(Ablk + (size_t)row * K + k0 + col);
            As[(col + 0) * GPAD + row] = a.x;
            As[(col + 1) * GPAD + row] = a.y;
            As[(col + 2) * GPAD + row] = a.z;
            As[(col + 3) * GPAD + row] = a.w;
            float4 w = *(const float4*)(Wblk + (size_t)row * K + k0 + col);
            Ws[(col + 0) * GPAD + row] = w.x;
            Ws[(col + 1) * GPAD + row] = w.y;
            Ws[(col + 2) * GPAD + row] = w.z;
            Ws[(col + 3) * GPAD + row] = w.w;
        }
        __syncthreads();
#pragma unroll 8
        for (int kk = 0; kk < GBK; kk++) {
            float ra[8], rb[8];
            *(float4*)&ra[0] = *(const float4*)&As[kk * GPAD + ty * 8];
            *(float4*)&ra[4] = *(const float4*)&As[kk * GPAD + ty * 8 + 4];
            *(float4*)&rb[0] = *(const float4*)&Ws[kk * GPAD + tx * 8];
            *(float4*)&rb[4] = *(const float4*)&Ws[kk * GPAD + tx * 8 + 4];
#pragma unroll
            for (int i = 0; i < 8; i++)
#pragma unroll
                for (int j = 0; j < 8; j++)
                    acc[i][j] += ra[i] * rb[j];
        }
        __syncthreads();
    }

#pragma unroll
    for (int i = 0; i < 8; i++) {
        int m = m0 + ty * 8 + i;
#pragma unroll
        for (int j = 0; j < 8; j++) {
            int n = n0 + tx * 8 + j;
            if (mode == 0) {
                C[(size_t)m * D_ + n] = acc[i][j];
            } else {
                int b = m >> 11, s = m & (S_ - 1);
                int h = n >> 7,  d = n & 127;
                C[(((size_t)b * H_ + h) * S_ + s) * HD_ + d] = acc[i][j];
            }
        }
    }
}

// ---------------- Flash attention (fp32) -------------------------------------
// Block: one head, 128 query rows. 256 threads (16x16).
// Per thread: S fragment 8 rows x 4 cols (cols tx+16j), O fragment 8x8 (cols tx+16u).
#define BQ  128
#define BKT 64
// smem: Qs[128][129] | KPs = union(Ks[64][129], Ps[128][65]) | Vs[64][129]
#define QS_FLOATS  (BQ * 129)
#define KPS_FLOATS (BQ * 65)          /* 8320 >= 64*129=8256 */
#define VS_FLOATS  (BKT * 129)
#define ATT_SMEM_BYTES ((QS_FLOATS + KPS_FLOATS + VS_FLOATS) * 4)

__global__ void __launch_bounds__(256) attn_kernel(const int* __restrict__ mask)
{
    extern __shared__ float sm[];
    float* Qs  = sm;
    float* KPs = sm + QS_FLOATS;
    float* Vs  = KPs + KPS_FLOATS;

    int bh = blockIdx.y;               // b*H + h
    int b = bh >> 4, h = bh & 15;
    int q0 = blockIdx.x * BQ;
    int tid = threadIdx.x;
    int tx = tid & 15, ty = tid >> 4;
    const float scale = 0.08838834764831843f;   // 1/sqrt(128)

    const float* Qg = g_Q + (size_t)bh * S_ * HD_ + (size_t)q0 * HD_;
    const float* Kg = g_K + (size_t)bh * S_ * HD_;
    const float* Vg = g_V + (size_t)bh * S_ * HD_;
    const int*   Mg = mask + (size_t)b * S_ * S_ + (size_t)q0 * S_;

    // Load Q tile, pre-scaled. 128x128 floats = 4096 float4, 16 per thread.
#pragma unroll
    for (int r = 0; r < 16; r++) {
        int idx = tid + 256 * r;
        int row = idx >> 5;            // 32 f4 per row
        int col = (idx & 31) << 2;
        float4 v = *(const float4*)(Qg + (size_t)row * HD_ + col);
        float* dst = Qs + row * 129 + col;
        dst[0] = v.x * scale; dst[1] = v.y * scale;
        dst[2] = v.z * scale; dst[3] = v.w * scale;
    }

    float m_run[8], l_run[8], accO[8][8];
#pragma unroll
    for (int i = 0; i < 8; i++) {
        m_run[i] = -INFINITY;
        l_run[i] = 0.f;
#pragma unroll
        for (int u = 0; u < 8; u++) accO[i][u] = 0.f;
    }

    for (int kt = 0; kt < S_; kt += BKT) {
        __syncthreads();               // previous PV reads of KPs/Vs done
        // Load K and V tiles: 64x128 floats = 2048 float4 each, 8 per thread.
#pragma unroll
        for (int r = 0; r < 8; r++) {
            int idx = tid + 256 * r;
            int row = idx >> 5;
            int col = (idx & 31) << 2;
            float4 kv = *(const float4*)(Kg + (size_t)(kt + row) * HD_ + col);
            float* kd = KPs + row * 129 + col;
            kd[0] = kv.x; kd[1] = kv.y; kd[2] = kv.z; kd[3] = kv.w;
            float4 vv = *(const float4*)(Vg + (size_t)(kt + row) * HD_ + col);
            float* vd = Vs + row * 129 + col;
            vd[0] = vv.x; vd[1] = vv.y; vd[2] = vv.z; vd[3] = vv.w;
        }
        __syncthreads();

        // S = (Q*scale) K^T : sv[8][4]
        float sv[8][4];
#pragma unroll
        for (int i = 0; i < 8; i++)
#pragma unroll
            for (int j = 0; j < 4; j++) sv[i][j] = 0.f;
#pragma unroll 4
        for (int d = 0; d < HD_; d++) {
            float qv[8], kv[4];
#pragma unroll
            for (int i = 0; i < 8; i++) qv[i] = Qs[(ty * 8 + i) * 129 + d];
#pragma unroll
            for (int j = 0; j < 4; j++) kv[j] = KPs[(tx + 16 * j) * 129 + d];
#pragma unroll
            for (int i = 0; i < 8; i++)
#pragma unroll
                for (int j = 0; j < 4; j++)
                    sv[i][j] += qv[i] * kv[j];
        }
        // mask (reference: score = -inf where mask==0)
#pragma unroll
        for (int i = 0; i < 8; i++)
#pragma unroll
            for (int j = 0; j < 4; j++)
                if (Mg[(size_t)(ty * 8 + i) * S_ + kt + tx + 16 * j] == 0)
                    sv[i][j] = -1e30f;

        // online softmax; row stats replicated across the 16-lane tx group
#pragma unroll
        for (int i = 0; i < 8; i++) {
            float mx = sv[i][0];
#pragma unroll
            for (int j = 1; j < 4; j++) mx = fmaxf(mx, sv[i][j]);
#pragma unroll
            for (int o = 8; o; o >>= 1)
                mx = fmaxf(mx, __shfl_xor_sync(0xffffffffu, mx, o));
            float mnew = fmaxf(m_run[i], mx);
            float corr = __expf(m_run[i] - mnew);
            m_run[i] = mnew;
            float ls = 0.f;
#pragma unroll
            for (int j = 0; j < 4; j++) {
                float p = __expf(sv[i][j] - mnew);
                sv[i][j] = p;
                ls += p;
            }
#pragma unroll
            for (int o = 8; o; o >>= 1)
                ls += __shfl_xor_sync(0xffffffffu, ls, o);
            l_run[i] = l_run[i] * corr + ls;
#pragma unroll
            for (int u = 0; u < 8; u++) accO[i][u] *= corr;
        }

        __syncthreads();               // all reads of KPs (as K) done
        // stage P into KPs as [128][65]
#pragma unroll
        for (int i = 0; i < 8; i++)
#pragma unroll
            for (int j = 0; j < 4; j++)
                KPs[(ty * 8 + i) * 65 + tx + 16 * j] = sv[i][j];
        __syncthreads();

        // O += P V
#pragma unroll 4
        for (int kk = 0; kk < BKT; kk++) {
            float pv[8], vv[8];
#pragma unroll
            for (int i = 0; i < 8; i++) pv[i] = KPs[(ty * 8 + i) * 65 + kk];
#pragma unroll
            for (int u = 0; u < 8; u++) vv[u] = Vs[kk * 129 + tx + 16 * u];
#pragma unroll
            for (int i = 0; i < 8; i++)
#pragma unroll
                for (int u = 0; u < 8; u++)
                    accO[i][u] += pv[i] * vv[u];
        }
    }

    // normalize + write to [B,S,D] layout
    float* Og = g_att + ((size_t)b * S_ + q0) * D_ + h * HD_;
#pragma unroll
    for (int i = 0; i < 8; i++) {
        float inv = 1.0f / l_run[i];
        int row = ty * 8 + i;
#pragma unroll
        for (int u = 0; u < 8; u++)
            Og[(size_t)row * D_ + tx + 16 * u] = accO[i][u] * inv;
    }
}

// ---------------- launch ------------------------------------------------------
extern "C" void kernel_launch(void* const* d_in, const int* in_sizes, int n_in,
                              void* d_out, int out_size)
{
    const float* query = (const float*)d_in[0];
    const float* key   = (const float*)d_in[1];
    const float* value = (const float*)d_in[2];
    const int*   mask  = (const int*)d_in[3];
    const float* wq    = (const float*)d_in[4];
    const float* wk    = (const float*)d_in[5];
    const float* wv    = (const float*)d_in[6];
    const float* wo    = (const float*)d_in[7];
    float* out = (float*)d_out;

    float *gQ, *gK, *gV, *gA;
    cudaGetSymbolAddress((void**)&gQ, g_Q);
    cudaGetSymbolAddress((void**)&gK, g_K);
    cudaGetSymbolAddress((void**)&gV, g_V);
    cudaGetSymbolAddress((void**)&gA, g_att);

    cudaFuncSetAttribute(attn_kernel,
                         cudaFuncAttributeMaxDynamicSharedMemorySize,
                         ATT_SMEM_BYTES);

    // RoPE tables
    rope_tables_kernel<<<(S_ * 64 + 255) / 256, 256>>>();

    // Projections (write head layout [B,H,S,hd])
    dim3 pg(D_ / 128, (B_ * S_) / 128);     // (16, 32)
    sgemm_kernel<<<pg, 256>>>(query, wq, gQ, 1);
    sgemm_kernel<<<pg, 256>>>(key,   wk, gK, 1);
    sgemm_kernel<<<pg, 256>>>(value, wv, gV, 1);

    // RoPE on Q and K (in place)
    rope_apply_kernel<<<(2 * B_ * H_ * S_ * 64) / 256, 256>>>();

    // Attention
    attn_kernel<<<dim3(S_ / BQ, B_ * H_), 256, ATT_SMEM_BYTES>>>(mask);

    // Output projection (plain [B,S,D] into d_out)
    sgemm_kernel<<<pg, 256>>>(gA, wo, out, 0);
}